// round 5
// baseline (speedup 1.0000x reference)
#include <cuda_runtime.h>
#include <math.h>

// ---------------- problem constants ----------------
#define BATCH  4
#define TSEQ   512
#define KDIM   512
#define HEADS  8
#define NBLK   4
#define VOCAB  32000
#define FFDIM  2048
#define BT     (BATCH*TSEQ)     // 2048 rows

// ---------------- scratch (device global, no runtime alloc) ----------------
#define SZ_H    (2048L*512)        // hidden
#define SZ_QKV  (2048L*4096)       // q / k / v / y
#define SZ_ATT  (32L*512*512)      // [b*h][q][s]
#define SZ_T1   (2048L*512)
#define SZ_FF   (2048L*2048)

#define OFF_H   0L
#define OFF_Q   (OFF_H   + SZ_H)
#define OFF_K   (OFF_Q   + SZ_QKV)
#define OFF_V   (OFF_K   + SZ_QKV)
#define OFF_ATT (OFF_V   + SZ_QKV)
#define OFF_Y   (OFF_ATT + SZ_ATT)
#define OFF_T1  (OFF_Y   + SZ_QKV)
#define OFF_FF  (OFF_T1  + SZ_T1)
#define SCRATCH_TOTAL (OFF_FF + SZ_FF)   // 48,234,496 floats (~184 MiB)

__device__ float g_scratch[SCRATCH_TOTAL];

// ---------------- helpers ----------------
__device__ __forceinline__ float warpRedSum(float v) {
    #pragma unroll
    for (int o = 16; o > 0; o >>= 1) v += __shfl_xor_sync(0xffffffffu, v, o);
    return v;
}
__device__ __forceinline__ float warpRedMax(float v) {
    #pragma unroll
    for (int o = 16; o > 0; o >>= 1) v = fmaxf(v, __shfl_xor_sync(0xffffffffu, v, o));
    return v;
}
__device__ __forceinline__ float gelu_exact(float x) {
    return 0.5f * x * (1.0f + erff(x * 0.70710678118654752f));
}

// ---------------- generic tiled SGEMM ----------------
// C[M,N] = alpha * A[M,K] * B   (+ bias[n]) (+ GELU)
// TB==0 : B is row-major [K,N], element (k,n) at B[k*ldb + n]
// TB==1 : B accessed transposed, element (k,n) at B[n*ldb + k]
// CAUSAL==1 : (scores) skip whole tiles strictly above the diagonal
// CAUSAL==2 : (att@V)  limit k-loop to k < m0+BM  (att rows are zero beyond q)
// Batch z = blockIdx.z is decomposed as bb = z/Hdiv, hh = z%Hdiv with
// per-operand strides (sXb, sXh) -> supports [b,t,h,d] layouts without copies.
#define BM 128
#define BN 128
#define BK 8

template<int TB, int ACT, int CAUSAL>
__global__ __launch_bounds__(256)
void sgemm_kernel(const float* __restrict__ A, int lda, long sAb, long sAh,
                  const float* __restrict__ Bm, int ldb, long sBb, long sBh,
                  const float* __restrict__ bias,
                  float* __restrict__ C, int ldc, long sCb, long sCh,
                  int M, int N, int Kd, int Hdiv, float alpha)
{
    const int bx = blockIdx.x, by = blockIdx.y, bz = blockIdx.z;
    if (CAUSAL == 1 && bx > by) return;   // fully-masked score tile

    const int bb = bz / Hdiv, hh = bz % Hdiv;
    A  += (long)bb * sAb + (long)hh * sAh;
    Bm += (long)bb * sBb + (long)hh * sBh;
    C  += (long)bb * sCb + (long)hh * sCh;

    __shared__ float As[2][BK][BM];
    __shared__ float Bs[2][BK][BN];

    const int tid = threadIdx.x;
    const int m0 = by * BM, n0 = bx * BN;

    int nk = Kd / BK;
    if (CAUSAL == 2) {
        int klim = m0 + BM; if (klim > Kd) klim = Kd;
        nk = (klim + BK - 1) / BK;
    }

    // A tile load mapping: 128 rows x 8 k  -> thread loads one float4
    const int arow = tid >> 1;            // 0..127
    const int acol = (tid & 1) * 4;       // 0 or 4
    const float* Aload = A + (long)(m0 + arow) * lda + acol;

    // B tile load mapping
    int brow, bcol;
    const float* Bload;
    if (TB) { brow = tid >> 1;  bcol = (tid & 1)  * 4; Bload = Bm + (long)(n0 + brow) * ldb + bcol; }
    else    { brow = tid >> 5;  bcol = (tid & 31) * 4; Bload = Bm + (long)brow * ldb + n0 + bcol; }

    // prologue: tile 0
    {
        float4 av = *(const float4*)(Aload);
        As[0][acol+0][arow] = av.x; As[0][acol+1][arow] = av.y;
        As[0][acol+2][arow] = av.z; As[0][acol+3][arow] = av.w;
        float4 bv = *(const float4*)(Bload);
        if (TB) {
            Bs[0][bcol+0][brow] = bv.x; Bs[0][bcol+1][brow] = bv.y;
            Bs[0][bcol+2][brow] = bv.z; Bs[0][bcol+3][brow] = bv.w;
        } else {
            *(float4*)&Bs[0][brow][bcol] = bv;
        }
    }
    __syncthreads();

    float acc[8][8];
    #pragma unroll
    for (int i = 0; i < 8; i++)
        #pragma unroll
        for (int j = 0; j < 8; j++) acc[i][j] = 0.0f;

    const int mb = (tid >> 4) * 8;   // 0..120
    const int nb = (tid & 15) * 8;   // 0..120

    for (int kt = 0; kt < nk; kt++) {
        const int buf = kt & 1;
        const bool pf = (kt + 1 < nk);
        float4 av, bv;
        if (pf) {
            av = *(const float4*)(Aload + (kt + 1) * BK);
            bv = TB ? *(const float4*)(Bload + (kt + 1) * BK)
                    : *(const float4*)(Bload + (long)(kt + 1) * BK * ldb);
        }
        #pragma unroll
        for (int kk = 0; kk < BK; kk++) {
            float a[8], b[8];
            *(float4*)(a)     = *(float4*)&As[buf][kk][mb];
            *(float4*)(a + 4) = *(float4*)&As[buf][kk][mb + 4];
            *(float4*)(b)     = *(float4*)&Bs[buf][kk][nb];
            *(float4*)(b + 4) = *(float4*)&Bs[buf][kk][nb + 4];
            #pragma unroll
            for (int i = 0; i < 8; i++)
                #pragma unroll
                for (int j = 0; j < 8; j++)
                    acc[i][j] += a[i] * b[j];
        }
        if (pf) {
            const int nbuf = buf ^ 1;
            As[nbuf][acol+0][arow] = av.x; As[nbuf][acol+1][arow] = av.y;
            As[nbuf][acol+2][arow] = av.z; As[nbuf][acol+3][arow] = av.w;
            if (TB) {
                Bs[nbuf][bcol+0][brow] = bv.x; Bs[nbuf][bcol+1][brow] = bv.y;
                Bs[nbuf][bcol+2][brow] = bv.z; Bs[nbuf][bcol+3][brow] = bv.w;
            } else {
                *(float4*)&Bs[nbuf][brow][bcol] = bv;
            }
        }
        __syncthreads();
    }

    // epilogue
    float bvv[8];
    if (bias) {
        #pragma unroll
        for (int j = 0; j < 8; j++) bvv[j] = bias[n0 + nb + j];
    } else {
        #pragma unroll
        for (int j = 0; j < 8; j++) bvv[j] = 0.0f;
    }
    #pragma unroll
    for (int i = 0; i < 8; i++) {
        float o[8];
        #pragma unroll
        for (int j = 0; j < 8; j++) {
            float v = acc[i][j] * alpha + bvv[j];
            if (ACT == 1) v = gelu_exact(v);
            o[j] = v;
        }
        float* cp = C + (long)(m0 + mb + i) * ldc + n0 + nb;
        *(float4*)(cp)     = *(float4*)(o);
        *(float4*)(cp + 4) = *(float4*)(o + 4);
    }
}

// ---------------- embedding + sinusoidal positional encoding ----------------
__global__ void embed_kernel(const int* __restrict__ x,
                             const float* __restrict__ eW,
                             float* __restrict__ h)
{
    long i = (long)blockIdx.x * blockDim.x + threadIdx.x;  // BT*K threads
    int d  = (int)(i & (KDIM - 1));
    long bt = i >> 9;                 // K = 512
    int t  = (int)(bt & (TSEQ - 1));
    int tok = x[bt];
    int j = d >> 1;
    // div = 10000 ** (2*(2j)/K) = 10000 ** (j/128)
    float div = powf(10000.0f, (float)j * (1.0f / 128.0f));
    float ang = (float)t / div;
    float p = (d & 1) ? cosf(ang) : sinf(ang);
    h[i] = eW[(long)tok * KDIM + d] + p;
}

// ---------------- causal softmax (row = one (b,h,q)) ----------------
__global__ __launch_bounds__(256)
void softmax_causal_kernel(float* __restrict__ att)
{
    __shared__ float red[8];
    const int r = blockIdx.x;                 // 0 .. B*H*T-1
    const int q = r & (TSEQ - 1);
    float* row = att + (long)r * TSEQ;
    const int tid = threadIdx.x;              // 256 threads, 2 elems each

    float x0 = (tid       <= q) ? row[tid]       : -3.0e38f;
    float x1 = (tid + 256 <= q) ? row[tid + 256] : -3.0e38f;

    float m = warpRedMax(fmaxf(x0, x1));
    if ((tid & 31) == 0) red[tid >> 5] = m;
    __syncthreads();
    m = red[0];
    #pragma unroll
    for (int i = 1; i < 8; i++) m = fmaxf(m, red[i]);
    __syncthreads();

    float e0 = (tid       <= q) ? expf(x0 - m) : 0.0f;
    float e1 = (tid + 256 <= q) ? expf(x1 - m) : 0.0f;

    float s = warpRedSum(e0 + e1);
    if ((tid & 31) == 0) red[tid >> 5] = s;
    __syncthreads();
    s = red[0];
    #pragma unroll
    for (int i = 1; i < 8; i++) s += red[i];

    float inv = 1.0f / s;
    row[tid]       = e0 * inv;   // zeros the masked region too (att@V reads it)
    row[tid + 256] = e1 * inv;
}

// ---------------- (residual +) LayerNorm, K=512, one block per row ----------
__global__ __launch_bounds__(256)
void ln_kernel(const float* __restrict__ in, const float* __restrict__ res,
               const float* __restrict__ w,  const float* __restrict__ b,
               float* __restrict__ out)
{
    __shared__ float red[8];
    const int r = blockIdx.x, tid = threadIdx.x;
    const long base = (long)r * KDIM;

    float x0 = in[base + tid], x1 = in[base + tid + 256];
    if (res) { x0 += res[base + tid]; x1 += res[base + tid + 256]; }

    float s = warpRedSum(x0 + x1);
    if ((tid & 31) == 0) red[tid >> 5] = s;
    __syncthreads();
    float tot = red[0];
    #pragma unroll
    for (int i = 1; i < 8; i++) tot += red[i];
    float mean = tot * (1.0f / (float)KDIM);
    __syncthreads();

    float d0 = x0 - mean, d1 = x1 - mean;
    float s2 = warpRedSum(d0 * d0 + d1 * d1);
    if ((tid & 31) == 0) red[tid >> 5] = s2;
    __syncthreads();
    float v = red[0];
    #pragma unroll
    for (int i = 1; i < 8; i++) v += red[i];
    v *= (1.0f / (float)KDIM);

    float inv = 1.0f / sqrtf(v + 1e-5f);
    out[base + tid]       = d0 * inv * w[tid]       + b[tid];
    out[base + tid + 256] = d1 * inv * w[tid + 256] + b[tid + 256];
}

// ---------------- launch ----------------
extern "C" void kernel_launch(void* const* d_in, const int* in_sizes, int n_in,
                              void* d_out, int out_size)
{
    (void)in_sizes; (void)n_in; (void)out_size;

    const int*   x      = (const int*)  d_in[0];
    const float* embedW = (const float*)d_in[1];
    const float* Wq     = (const float*)d_in[2];
    const float* Wk     = (const float*)d_in[3];
    const float* Wv     = (const float*)d_in[4];
    const float* Wu     = (const float*)d_in[5];
    const float* bu     = (const float*)d_in[6];
    const float* W1     = (const float*)d_in[7];
    const float* b1     = (const float*)d_in[8];
    const float* W2     = (const float*)d_in[9];
    const float* b2     = (const float*)d_in[10];
    const float* ln1w   = (const float*)d_in[11];
    const float* ln1b   = (const float*)d_in[12];
    const float* ln2w   = (const float*)d_in[13];
    const float* ln2b   = (const float*)d_in[14];
    const float* lnfw   = (const float*)d_in[15];
    const float* lnfb   = (const float*)d_in[16];
    const float* uW     = (const float*)d_in[17];
    const float* ub     = (const float*)d_in[18];
    float* outp = (float*)d_out;

    void* sp = nullptr;
    cudaGetSymbolAddress(&sp, g_scratch);
    float* S    = (float*)sp;
    float* hbuf = S + OFF_H;
    float* qb   = S + OFF_Q;
    float* kb   = S + OFF_K;
    float* vb   = S + OFF_V;
    float* attb = S + OFF_ATT;
    float* yb   = S + OFF_Y;
    float* t1   = S + OFF_T1;
    float* ffb  = S + OFF_FF;

    const float inv_sqrt_k = 0.04419417382415922f;  // 1/sqrt(512)

    embed_kernel<<<(BT * KDIM) / 256, 256>>>(x, embedW, hbuf);

    const dim3 blk(256);
    const dim3 gQKV(4096 / BN, BT / BM, 1);          // 32 x 16
    const dim3 gATT(TSEQ / BN, TSEQ / BM, BATCH * HEADS);  // 4 x 4 x 32
    const dim3 gOUT(512  / BN, BT / BM, 1);          // 4 x 16
    const dim3 gFF1(FFDIM / BN, BT / BM, 1);         // 16 x 16

    for (int i = 0; i < NBLK; i++) {
        const long wqkvOff = (long)i * KDIM * (KDIM * HEADS);  // 2,097,152
        const long w1Off   = (long)i * KDIM * FFDIM;           // 1,048,576
        const long w2Off   = (long)i * FFDIM * KDIM;

        // QKV projections: [2048,512] x [512,4096]
        sgemm_kernel<0,0,0><<<gQKV, blk>>>(hbuf, KDIM, 0, 0,
            Wq + wqkvOff, KDIM*HEADS, 0, 0, nullptr,
            qb, KDIM*HEADS, 0, 0, BT, KDIM*HEADS, KDIM, 1, 1.0f);
        sgemm_kernel<0,0,0><<<gQKV, blk>>>(hbuf, KDIM, 0, 0,
            Wk + wqkvOff, KDIM*HEADS, 0, 0, nullptr,
            kb, KDIM*HEADS, 0, 0, BT, KDIM*HEADS, KDIM, 1, 1.0f);
        sgemm_kernel<0,0,0><<<gQKV, blk>>>(hbuf, KDIM, 0, 0,
            Wv + wqkvOff, KDIM*HEADS, 0, 0, nullptr,
            vb, KDIM*HEADS, 0, 0, BT, KDIM*HEADS, KDIM, 1, 1.0f);

        // scores[z][q][s] = (Q . K) / sqrt(k), z = b*H + h, causal tile skip
        sgemm_kernel<1,0,1><<<gATT, blk>>>(
            qb, KDIM*HEADS, (long)TSEQ*KDIM*HEADS, (long)KDIM,
            kb, KDIM*HEADS, (long)TSEQ*KDIM*HEADS, (long)KDIM,
            nullptr,
            attb, TSEQ, (long)HEADS*TSEQ*TSEQ, (long)TSEQ*TSEQ,
            TSEQ, TSEQ, KDIM, HEADS, inv_sqrt_k);

        softmax_causal_kernel<<<BATCH * HEADS * TSEQ, blk>>>(attb);

        // y[b,q,h,d] = att @ V, k-loop limited by causal zero structure
        sgemm_kernel<0,0,2><<<gATT, blk>>>(
            attb, TSEQ, (long)HEADS*TSEQ*TSEQ, (long)TSEQ*TSEQ,
            vb, KDIM*HEADS, (long)TSEQ*KDIM*HEADS, (long)KDIM,
            nullptr,
            yb, KDIM*HEADS, (long)TSEQ*KDIM*HEADS, (long)KDIM,
            TSEQ, TSEQ, KDIM, HEADS, 1.0f);

        // attn out proj: [2048,4096] x [4096,512] + bu
        sgemm_kernel<0,0,0><<<gOUT, blk>>>(yb, KDIM*HEADS, 0, 0,
            Wu + wqkvOff, KDIM, 0, 0, bu + (long)i*KDIM,
            t1, KDIM, 0, 0, BT, KDIM, KDIM*HEADS, 1, 1.0f);

        // h = LN(attn_out + h)
        ln_kernel<<<BT, blk>>>(t1, hbuf, ln1w + (long)i*KDIM, ln1b + (long)i*KDIM, hbuf);

        // FFN up + exact GELU: [2048,512] x [512,2048]
        sgemm_kernel<0,1,0><<<gFF1, blk>>>(hbuf, KDIM, 0, 0,
            W1 + w1Off, FFDIM, 0, 0, b1 + (long)i*FFDIM,
            ffb, FFDIM, 0, 0, BT, FFDIM, KDIM, 1, 1.0f);

        // FFN down: [2048,2048] x [2048,512]
        sgemm_kernel<0,0,0><<<gOUT, blk>>>(ffb, FFDIM, 0, 0,
            W2 + w2Off, KDIM, 0, 0, b2 + (long)i*KDIM,
            t1, KDIM, 0, 0, BT, KDIM, FFDIM, 1, 1.0f);

        // h = LN(ff_out + h)
        ln_kernel<<<BT, blk>>>(t1, hbuf, ln2w + (long)i*KDIM, ln2b + (long)i*KDIM, hbuf);
    }

    // final LN (no residual)
    ln_kernel<<<BT, blk>>>(hbuf, nullptr, lnfw, lnfb, hbuf);

    // unembed: [2048,512] x [512,32000] + b
    const dim3 gUN(VOCAB / BN, BT / BM, 1);  // 250 x 16
    sgemm_kernel<0,0,0><<<gUN, blk>>>(hbuf, KDIM, 0, 0,
        uW, VOCAB, 0, 0, ub,
        outp, VOCAB, 0, 0, BT, VOCAB, KDIM, 1, 1.0f);
}

// round 8
// speedup vs baseline: 2.2450x; 2.2450x over previous
#include <cuda_runtime.h>
#include <cuda_bf16.h>
#include <math.h>
#include <stdint.h>

#define TSEQ 512
#define KDIM 512
#define VOCAB 32000
#define BT 2048

// ---------- scratch pools ----------
constexpr long E_H = 2048L*512, E_QKV = 2048L*4096, E_ATT = 32L*512*512,
               E_FF = 2048L*2048, E_W3 = 4L*4096*512, E_W12 = 4L*2048*512,
               E_UN = 32000L*512;
constexpr long O_HHI=0, O_HLO=O_HHI+E_H,
 O_QHI=O_HLO+E_H, O_QLO=O_QHI+E_QKV, O_KHI=O_QLO+E_QKV, O_KLO=O_KHI+E_QKV,
 O_VTHI=O_KLO+E_QKV, O_VTLO=O_VTHI+E_ATT, O_ATHI=O_VTLO+E_ATT, O_ATLO=O_ATHI+E_ATT,
 O_YHI=O_ATLO+E_ATT, O_YLO=O_YHI+E_QKV, O_FHI=O_YLO+E_QKV, O_FLO=O_FHI+E_FF,
 O_WQHI=O_FLO+E_FF, O_WQLO=O_WQHI+E_W3, O_WKHI=O_WQLO+E_W3, O_WKLO=O_WKHI+E_W3,
 O_WVHI=O_WKLO+E_W3, O_WVLO=O_WVHI+E_W3, O_WUHI=O_WVLO+E_W3, O_WULO=O_WUHI+E_W3,
 O_W1HI=O_WULO+E_W3, O_W1LO=O_W1HI+E_W12, O_W2HI=O_W1LO+E_W12, O_W2LO=O_W2HI+E_W12,
 O_UNHI=O_W2LO+E_W12, O_UNLO=O_UNHI+E_UN, BF_TOTAL=O_UNLO+E_UN;
__device__ __nv_bfloat16 g_bf[BF_TOTAL];

constexpr long F_H=0, F_V=F_H+E_H, F_ATT=F_V+E_QKV, F_T1=F_ATT+E_ATT,
               F_TOTAL=F_T1+E_H;
__device__ float g_f[F_TOTAL];

// ---------- helpers ----------
__device__ __forceinline__ uint32_t s2u(const void* p) {
    uint32_t a;
    asm("{ .reg .u64 t; cvta.to.shared.u64 t, %1; cvt.u32.u64 %0, t; }" : "=r"(a) : "l"(p));
    return a;
}
__device__ __forceinline__ void ldm4(uint32_t& r0, uint32_t& r1, uint32_t& r2, uint32_t& r3,
                                     uint32_t addr) {
    asm volatile("ldmatrix.sync.aligned.m8n8.x4.shared.b16 {%0,%1,%2,%3}, [%4];"
                 : "=r"(r0), "=r"(r1), "=r"(r2), "=r"(r3) : "r"(addr));
}
__device__ __forceinline__ void mma16816(float* c, uint32_t a0, uint32_t a1, uint32_t a2,
                                         uint32_t a3, uint32_t b0, uint32_t b1) {
    asm volatile(
        "mma.sync.aligned.m16n8k16.row.col.f32.bf16.bf16.f32 "
        "{%0,%1,%2,%3}, {%4,%5,%6,%7}, {%8,%9}, {%0,%1,%2,%3};"
        : "+f"(c[0]), "+f"(c[1]), "+f"(c[2]), "+f"(c[3])
        : "r"(a0), "r"(a1), "r"(a2), "r"(a3), "r"(b0), "r"(b1));
}
__device__ __forceinline__ void cpa16(uint32_t dst, const void* src) {
    asm volatile("cp.async.cg.shared.global [%0], [%1], 16;" :: "r"(dst), "l"(src));
}
__device__ __forceinline__ void cpcommit() { asm volatile("cp.async.commit_group;"); }
__device__ __forceinline__ void cpwait0() { asm volatile("cp.async.wait_group 0;"); }
__device__ __forceinline__ void cpwait1() { asm volatile("cp.async.wait_group 1;"); }

__device__ __forceinline__ float gelu_exact(float x) {
    return 0.5f * x * (1.0f + erff(x * 0.70710678118654752f));
}
__device__ __forceinline__ void split_st(float v, __nv_bfloat16* hp, __nv_bfloat16* lp) {
    __nv_bfloat16 h = __float2bfloat16(v);
    *hp = h; *lp = __float2bfloat16(v - __bfloat162float(h));
}
__device__ __forceinline__ uint32_t pack_hi(float a, float b) {
    __nv_bfloat16 h0 = __float2bfloat16(a), h1 = __float2bfloat16(b);
    return (uint32_t)*(uint16_t*)&h0 | ((uint32_t)*(uint16_t*)&h1 << 16);
}
__device__ __forceinline__ uint32_t pack_lo(float a, float b) {
    __nv_bfloat16 h0 = __float2bfloat16(a), h1 = __float2bfloat16(b);
    float r0 = a - __bfloat162float(h0), r1 = b - __bfloat162float(h1);
    __nv_bfloat16 l0 = __float2bfloat16(r0), l1 = __float2bfloat16(r1);
    return (uint32_t)*(uint16_t*)&l0 | ((uint32_t)*(uint16_t*)&l1 << 16);
}
__device__ __forceinline__ float wSum(float v) {
    #pragma unroll
    for (int o = 16; o > 0; o >>= 1) v += __shfl_xor_sync(~0u, v, o);
    return v;
}
__device__ __forceinline__ float wMax(float v) {
    #pragma unroll
    for (int o = 16; o > 0; o >>= 1) v = fmaxf(v, __shfl_xor_sync(~0u, v, o));
    return v;
}

// ---------- split-bf16 HMMA GEMM: C[M,N] = alpha*A[M,K]*B[N,K]^T ----------
// 128x128 CTA tile, 8 warps (2x4), warp tile 64x32, K-chunk 32, cp.async 2-stage.
// SMEM plane: 128 rows x 80B (32 bf16 + 16B pad) -> ldmatrix conflict-free.
constexpr int ROWB = 80;                   // bytes per smem row
constexpr int PL   = 128 * ROWB;           // plane: 10240 B
constexpr int STGB = 4 * PL;               // Ah,Al,Bh,Bl: 40960 B
constexpr int SMEMB = 2 * STGB;            // 81920 B

template<bool SPLIT, bool BIAS, bool GELU, int CAUSAL>
__global__ void __launch_bounds__(256, 1)
tc_gemm(const __nv_bfloat16* __restrict__ Ah, const __nv_bfloat16* __restrict__ Al,
        int lda, long sAb, long sAh,
        const __nv_bfloat16* __restrict__ Bh, const __nv_bfloat16* __restrict__ Bl,
        int ldb, long sBb, long sBh,
        const float* __restrict__ bias,
        float* __restrict__ Cf, __nv_bfloat16* __restrict__ Chi, __nv_bfloat16* __restrict__ Clo,
        int ldc, long sCb, long sCh, int Kd, int Hdiv, float alpha)
{
    const int m0 = blockIdx.y * 128, n0 = blockIdx.x * 128;
    if (CAUSAL == 1 && n0 > m0 + 127) return;

    const int bz = blockIdx.z, bb = bz / Hdiv, hh = bz - bb * Hdiv;
    Ah += (long)bb*sAb + (long)hh*sAh;  Al += (long)bb*sAb + (long)hh*sAh;
    Bh += (long)bb*sBb + (long)hh*sBh;  Bl += (long)bb*sBb + (long)hh*sBh;
    const long coff = (long)bb*sCb + (long)hh*sCh;

    extern __shared__ char smem[];
    const uint32_t sb = s2u(smem);
    const int tid = threadIdx.x, wid = tid >> 5, lane = tid & 31;
    const int wm = wid >> 2, wn = wid & 3;   // 2x4 warp grid

    int nk = Kd >> 5;
    if (CAUSAL == 2) { int kl = m0 + 128; if (kl > Kd) kl = Kd; nk = kl >> 5; }

    // per-thread load mapping: 2048 16B-chunks per stage, 8 iters x 256 threads
    // id: plane = id>>9, rem = id&511, r = rem>>2, c = rem&3
    const int lp0 = tid >> 9;  // always 0; kept for clarity of id decomposition below

    float acc[4][4][4];
    #pragma unroll
    for (int i = 0; i < 4; i++)
        #pragma unroll
        for (int j = 0; j < 4; j++)
            #pragma unroll
            for (int q = 0; q < 4; q++) acc[i][j][q] = 0.0f;
    (void)lp0;

    // ---- stage loader ----
    auto load_stage = [&](int st, int kt) {
        const int k0 = kt << 5;
        const uint32_t base = sb + st * STGB;
        #pragma unroll
        for (int it = 0; it < 8; it++) {
            int id = it * 256 + tid;
            int plane = id >> 9, rem = id & 511, r = rem >> 2, c = rem & 3;
            const __nv_bfloat16* src;
            long off;
            if (plane < 2) {
                src = plane ? Al : Ah;
                off = (long)(m0 + r) * lda + k0 + c * 8;
            } else {
                src = (plane == 3) ? Bl : Bh;
                off = (long)(n0 + r) * ldb + k0 + c * 8;
            }
            cpa16(base + plane * PL + r * ROWB + c * 16, src + off);
        }
    };

    load_stage(0, 0);
    cpcommit();

    for (int kt = 0; kt < nk; kt++) {
        const int st = kt & 1;
        if (kt + 1 < nk) { load_stage(st ^ 1, kt + 1); cpcommit(); cpwait1(); }
        else cpwait0();
        __syncthreads();

        const uint32_t stg = sb + st * STGB;
        #pragma unroll
        for (int kk = 0; kk < 2; kk++) {
            // A fragments: row = wm*64 + mf*16 + (lane&15); kbytes = kk*32 + (lane>>4)*16
            uint32_t ah[4][4], al[4][4];
            {
                const uint32_t rofs = (uint32_t)(wm * 64 + (lane & 15)) * ROWB
                                    + kk * 32 + ((lane >> 4) << 4);
                #pragma unroll
                for (int mf = 0; mf < 4; mf++) {
                    uint32_t ad = stg + rofs + (uint32_t)(mf * 16) * ROWB;
                    ldm4(ah[mf][0], ah[mf][1], ah[mf][2], ah[mf][3], ad);
                    ldm4(al[mf][0], al[mf][1], al[mf][2], al[mf][3], ad + PL);
                }
            }
            // B fragments: x4 covers 16 n-rows (2 nfrags)
            // lane q=lane>>3: row_n += 8 if q>=2, kbytes += 16 if q&1
            uint32_t bh[4][2], bl[4][2];
            {
                const int q = lane >> 3, w8 = lane & 7;
                const uint32_t rofs = (uint32_t)(wn * 32 + w8 + ((q >> 1) << 3)) * ROWB
                                    + kk * 32 + ((q & 1) << 4);
                #pragma unroll
                for (int np = 0; np < 2; np++) {
                    uint32_t bd = stg + 2 * PL + rofs + (uint32_t)(np * 16) * ROWB;
                    uint32_t r0, r1, r2, r3;
                    ldm4(r0, r1, r2, r3, bd);
                    bh[np*2][0] = r0; bh[np*2][1] = r1;
                    bh[np*2+1][0] = r2; bh[np*2+1][1] = r3;
                    ldm4(r0, r1, r2, r3, bd + PL);
                    bl[np*2][0] = r0; bl[np*2][1] = r1;
                    bl[np*2+1][0] = r2; bl[np*2+1][1] = r3;
                }
            }
            #pragma unroll
            for (int mf = 0; mf < 4; mf++)
                #pragma unroll
                for (int nf = 0; nf < 4; nf++) {
                    mma16816(acc[mf][nf], ah[mf][0], ah[mf][1], ah[mf][2], ah[mf][3],
                             bh[nf][0], bh[nf][1]);
                    mma16816(acc[mf][nf], ah[mf][0], ah[mf][1], ah[mf][2], ah[mf][3],
                             bl[nf][0], bl[nf][1]);
                    mma16816(acc[mf][nf], al[mf][0], al[mf][1], al[mf][2], al[mf][3],
                             bh[nf][0], bh[nf][1]);
                }
        }
        __syncthreads();
    }

    // ---- epilogue ----
    const int mbase = m0 + wm * 64 + (lane >> 2);
    const int nbase = n0 + wn * 32 + (lane & 3) * 2;
    #pragma unroll
    for (int mf = 0; mf < 4; mf++) {
        #pragma unroll
        for (int nf = 0; nf < 4; nf++) {
            const int m = mbase + mf * 16, n = nbase + nf * 8;
            float v0 = acc[mf][nf][0] * alpha, v1 = acc[mf][nf][1] * alpha;
            float v2 = acc[mf][nf][2] * alpha, v3 = acc[mf][nf][3] * alpha;
            if (BIAS) {
                float bb0 = bias[n], bb1 = bias[n + 1];
                v0 += bb0; v1 += bb1; v2 += bb0; v3 += bb1;
            }
            if (GELU) {
                v0 = gelu_exact(v0); v1 = gelu_exact(v1);
                v2 = gelu_exact(v2); v3 = gelu_exact(v3);
            }
            const long r0 = coff + (long)m * ldc + n;
            const long r1 = coff + (long)(m + 8) * ldc + n;
            if (!SPLIT) {
                *(float2*)(Cf + r0) = make_float2(v0, v1);
                *(float2*)(Cf + r1) = make_float2(v2, v3);
            } else {
                *(uint32_t*)(Chi + r0) = pack_hi(v0, v1);
                *(uint32_t*)(Clo + r0) = pack_lo(v0, v1);
                *(uint32_t*)(Chi + r1) = pack_hi(v2, v3);
                *(uint32_t*)(Clo + r1) = pack_lo(v2, v3);
            }
        }
    }
}

// ---------- transpose + split: out[C,R] = in[R,C] ----------
__global__ void tsplit_ker(const float* __restrict__ in, int ldin, long sInB, long sInH,
                           __nv_bfloat16* __restrict__ oh, __nv_bfloat16* __restrict__ ol,
                           int ldout, long sOutB, long sOutH, int Hdiv)
{
    __shared__ float t[32][33];
    const int bz = blockIdx.z, bb = bz / Hdiv, hh = bz - bb * Hdiv;
    in += (long)bb*sInB + (long)hh*sInH;
    oh += (long)bb*sOutB + (long)hh*sOutH;
    ol += (long)bb*sOutB + (long)hh*sOutH;
    const int c0 = blockIdx.x * 32, r0 = blockIdx.y * 32;
    const int tx = threadIdx.x, ty = threadIdx.y;
    #pragma unroll
    for (int i = 0; i < 4; i++) {
        int r = ty + i * 8;
        t[r][tx] = in[(long)(r0 + r) * ldin + c0 + tx];
    }
    __syncthreads();
    #pragma unroll
    for (int i = 0; i < 4; i++) {
        int rr = ty + i * 8;
        long o = (long)(c0 + rr) * ldout + r0 + tx;
        split_st(t[tx][rr], oh + o, ol + o);
    }
}

// ---------- embed + positional ----------
__global__ void embed_ker(const int* __restrict__ x, const float* __restrict__ eW,
                          float* __restrict__ h,
                          __nv_bfloat16* __restrict__ hh, __nv_bfloat16* __restrict__ hl)
{
    long i = (long)blockIdx.x * blockDim.x + threadIdx.x;
    int d = (int)(i & 511);
    long bt = i >> 9;
    int t = (int)(bt & 511);
    int tok = x[bt];
    int j = d >> 1;
    float div = powf(10000.0f, (float)j * (1.0f / 128.0f));
    float ang = (float)t / div;
    float p = (d & 1) ? cosf(ang) : sinf(ang);
    float v = eW[(long)tok * 512 + d] + p;
    h[i] = v;
    split_st(v, hh + i, hl + i);
}

// ---------- causal softmax -> split ----------
__global__ void __launch_bounds__(256)
softmax_ker(const float* __restrict__ att,
            __nv_bfloat16* __restrict__ oh, __nv_bfloat16* __restrict__ ol)
{
    __shared__ float red[8];
    const int r = blockIdx.x, q = r & 511, tid = threadIdx.x;
    const float* row = att + (long)r * 512;
    float x0 = (tid       <= q) ? row[tid]       : -3.0e38f;
    float x1 = (tid + 256 <= q) ? row[tid + 256] : -3.0e38f;
    float m = wMax(fmaxf(x0, x1));
    if ((tid & 31) == 0) red[tid >> 5] = m;
    __syncthreads();
    m = red[0];
    #pragma unroll
    for (int i = 1; i < 8; i++) m = fmaxf(m, red[i]);
    __syncthreads();
    float e0 = (tid       <= q) ? expf(x0 - m) : 0.0f;
    float e1 = (tid + 256 <= q) ? expf(x1 - m) : 0.0f;
    float s = wSum(e0 + e1);
    if ((tid & 31) == 0) red[tid >> 5] = s;
    __syncthreads();
    s = red[0];
    #pragma unroll
    for (int i = 1; i < 8; i++) s += red[i];
    float inv = 1.0f / s;
    long base = (long)r * 512;
    split_st(e0 * inv, oh + base + tid,       ol + base + tid);
    split_st(e1 * inv, oh + base + tid + 256, ol + base + tid + 256);
}

// ---------- (residual+) LayerNorm -> fp32 + split ----------
__global__ void __launch_bounds__(256)
ln_ker(const float* __restrict__ in, const float* __restrict__ res,
       const float* __restrict__ w, const float* __restrict__ b,
       float* __restrict__ out, __nv_bfloat16* __restrict__ oh, __nv_bfloat16* __restrict__ ol)
{
    __shared__ float red[8];
    const int r = blockIdx.x, tid = threadIdx.x;
    const long base = (long)r * 512;
    float x0 = in[base + tid], x1 = in[base + tid + 256];
    if (res) { x0 += res[base + tid]; x1 += res[base + tid + 256]; }
    float s = wSum(x0 + x1);
    if ((tid & 31) == 0) red[tid >> 5] = s;
    __syncthreads();
    float tot = red[0];
    #pragma unroll
    for (int i = 1; i < 8; i++) tot += red[i];
    float mean = tot * (1.0f / 512.0f);
    __syncthreads();
    float d0 = x0 - mean, d1 = x1 - mean;
    float s2 = wSum(d0 * d0 + d1 * d1);
    if ((tid & 31) == 0) red[tid >> 5] = s2;
    __syncthreads();
    float v = red[0];
    #pragma unroll
    for (int i = 1; i < 8; i++) v += red[i];
    float inv = 1.0f / sqrtf(v * (1.0f / 512.0f) + 1e-5f);
    float y0 = d0 * inv * w[tid]       + b[tid];
    float y1 = d1 * inv * w[tid + 256] + b[tid + 256];
    out[base + tid] = y0; out[base + tid + 256] = y1;
    split_st(y0, oh + base + tid,       ol + base + tid);
    split_st(y1, oh + base + tid + 256, ol + base + tid + 256);
}

// ---------- launch ----------
extern "C" void kernel_launch(void* const* d_in, const int* in_sizes, int n_in,
                              void* d_out, int out_size)
{
    (void)in_sizes; (void)n_in; (void)out_size;
    const int*   x    = (const int*)  d_in[0];
    const float* eW   = (const float*)d_in[1];
    const float* Wq   = (const float*)d_in[2];
    const float* Wk   = (const float*)d_in[3];
    const float* Wv   = (const float*)d_in[4];
    const float* Wu   = (const float*)d_in[5];
    const float* bu   = (const float*)d_in[6];
    const float* W1   = (const float*)d_in[7];
    const float* b1   = (const float*)d_in[8];
    const float* W2   = (const float*)d_in[9];
    const float* b2   = (const float*)d_in[10];
    const float* ln1w = (const float*)d_in[11];
    const float* ln1b = (const float*)d_in[12];
    const float* ln2w = (const float*)d_in[13];
    const float* ln2b = (const float*)d_in[14];
    const float* lnfw = (const float*)d_in[15];
    const float* lnfb = (const float*)d_in[16];
    const float* uW   = (const float*)d_in[17];
    const float* ub   = (const float*)d_in[18];
    float* outp = (float*)d_out;

    void *pb = nullptr, *pf = nullptr;
    cudaGetSymbolAddress(&pb, g_bf);
    cudaGetSymbolAddress(&pf, g_f);
    __nv_bfloat16* B = (__nv_bfloat16*)pb;
    float* F = (float*)pf;

    cudaFuncSetAttribute(tc_gemm<true,false,false,0>, cudaFuncAttributeMaxDynamicSharedMemorySize, SMEMB);
    cudaFuncSetAttribute(tc_gemm<false,false,false,0>, cudaFuncAttributeMaxDynamicSharedMemorySize, SMEMB);
    cudaFuncSetAttribute(tc_gemm<false,false,false,1>, cudaFuncAttributeMaxDynamicSharedMemorySize, SMEMB);
    cudaFuncSetAttribute(tc_gemm<true,false,false,2>, cudaFuncAttributeMaxDynamicSharedMemorySize, SMEMB);
    cudaFuncSetAttribute(tc_gemm<false,true,false,0>, cudaFuncAttributeMaxDynamicSharedMemorySize, SMEMB);
    cudaFuncSetAttribute(tc_gemm<true,true,true,0>, cudaFuncAttributeMaxDynamicSharedMemorySize, SMEMB);

    const dim3 t8(32, 8);
    // weight transpose+split
    tsplit_ker<<<dim3(128,16,4), t8>>>(Wq, 4096, 512L*4096, 0, B+O_WQHI, B+O_WQLO, 512, 4096L*512, 0, 1);
    tsplit_ker<<<dim3(128,16,4), t8>>>(Wk, 4096, 512L*4096, 0, B+O_WKHI, B+O_WKLO, 512, 4096L*512, 0, 1);
    tsplit_ker<<<dim3(128,16,4), t8>>>(Wv, 4096, 512L*4096, 0, B+O_WVHI, B+O_WVLO, 512, 4096L*512, 0, 1);
    tsplit_ker<<<dim3(16,128,4), t8>>>(Wu,  512, 4096L*512, 0, B+O_WUHI, B+O_WULO, 4096, 512L*4096, 0, 1);
    tsplit_ker<<<dim3(64,16,4),  t8>>>(W1, 2048, 512L*2048, 0, B+O_W1HI, B+O_W1LO, 512, 2048L*512, 0, 1);
    tsplit_ker<<<dim3(16,64,4),  t8>>>(W2,  512, 2048L*512, 0, B+O_W2HI, B+O_W2LO, 2048, 512L*2048, 0, 1);
    tsplit_ker<<<dim3(1000,16,1),t8>>>(uW, 32000, 0, 0, B+O_UNHI, B+O_UNLO, 512, 0, 0, 1);

    embed_ker<<<(BT*512)/256, 256>>>(x, eW, F+F_H, B+O_HHI, B+O_HLO);

    const float isk = 0.04419417382415922f; // 1/sqrt(512)
    const dim3 gQKV(32,16,1), gATT(4,4,32), gOUT(4,16,1), gFF(16,16,1);

    for (int i = 0; i < 4; i++) {
        const long w3 = (long)i * 4096 * 512, w12 = (long)i * 2048 * 512;
        tc_gemm<true,false,false,0><<<gQKV,256,SMEMB>>>(B+O_HHI, B+O_HLO, 512,0,0,
            B+O_WQHI+w3, B+O_WQLO+w3, 512,0,0, nullptr,
            nullptr, B+O_QHI, B+O_QLO, 4096,0,0, 512, 1, 1.0f);
        tc_gemm<true,false,false,0><<<gQKV,256,SMEMB>>>(B+O_HHI, B+O_HLO, 512,0,0,
            B+O_WKHI+w3, B+O_WKLO+w3, 512,0,0, nullptr,
            nullptr, B+O_KHI, B+O_KLO, 4096,0,0, 512, 1, 1.0f);
        tc_gemm<false,false,false,0><<<gQKV,256,SMEMB>>>(B+O_HHI, B+O_HLO, 512,0,0,
            B+O_WVHI+w3, B+O_WVLO+w3, 512,0,0, nullptr,
            F+F_V, nullptr, nullptr, 4096,0,0, 512, 1, 1.0f);
        // V^T split per (b,h): [t,d] -> [d,t]
        tsplit_ker<<<dim3(16,16,32), t8>>>(F+F_V, 4096, 512L*4096, 512,
            B+O_VTHI, B+O_VTLO, 512, 8L*512*512, 512L*512, 8);
        // scores = Q K^T / sqrt(k), causal tile skip
        tc_gemm<false,false,false,1><<<gATT,256,SMEMB>>>(
            B+O_QHI, B+O_QLO, 4096, 512L*4096, 512,
            B+O_KHI, B+O_KLO, 4096, 512L*4096, 512, nullptr,
            F+F_ATT, nullptr, nullptr, 512, 8L*512*512, 512L*512, 512, 8, isk);
        softmax_ker<<<32*512, 256>>>(F+F_ATT, B+O_ATHI, B+O_ATLO);
        // y = att @ V (K-limit from causality)
        tc_gemm<true,false,false,2><<<gATT,256,SMEMB>>>(
            B+O_ATHI, B+O_ATLO, 512, 8L*512*512, 512L*512,
            B+O_VTHI, B+O_VTLO, 512, 8L*512*512, 512L*512, nullptr,
            nullptr, B+O_YHI, B+O_YLO, 4096, 512L*4096, 512, 512, 8, 1.0f);
        // out proj + bu -> fp32 t1
        tc_gemm<false,true,false,0><<<gOUT,256,SMEMB>>>(B+O_YHI, B+O_YLO, 4096,0,0,
            B+O_WUHI+w3, B+O_WULO+w3, 4096,0,0, bu + (long)i*512,
            F+F_T1, nullptr, nullptr, 512,0,0, 4096, 1, 1.0f);
        ln_ker<<<BT,256>>>(F+F_T1, F+F_H, ln1w+(long)i*512, ln1b+(long)i*512,
                           F+F_H, B+O_HHI, B+O_HLO);
        // FFN up + GELU (split out)
        tc_gemm<true,true,true,0><<<gFF,256,SMEMB>>>(B+O_HHI, B+O_HLO, 512,0,0,
            B+O_W1HI+w12, B+O_W1LO+w12, 512,0,0, b1 + (long)i*2048,
            nullptr, B+O_FHI, B+O_FLO, 2048,0,0, 512, 1, 1.0f);
        // FFN down + b2 -> fp32 t1
        tc_gemm<false,true,false,0><<<gOUT,256,SMEMB>>>(B+O_FHI, B+O_FLO, 2048,0,0,
            B+O_W2HI+w12, B+O_W2LO+w12, 2048,0,0, b2 + (long)i*512,
            F+F_T1, nullptr, nullptr, 512,0,0, 2048, 1, 1.0f);
        ln_ker<<<BT,256>>>(F+F_T1, F+F_H, ln2w+(long)i*512, ln2b+(long)i*512,
                           F+F_H, B+O_HHI, B+O_HLO);
    }
    // final LN (no residual)
    ln_ker<<<BT,256>>>(F+F_H, nullptr, lnfw, lnfb, F+F_T1, B+O_HHI, B+O_HLO);
    // unembed
    tc_gemm<false,true,false,0><<<dim3(250,16,1),256,SMEMB>>>(B+O_HHI, B+O_HLO, 512,0,0,
        B+O_UNHI, B+O_UNLO, 512,0,0, ub,
        outp, nullptr, nullptr, 32000,0,0, 512, 1, 1.0f);
}

// round 10
// speedup vs baseline: 2.7137x; 1.2088x over previous
#include <cuda_runtime.h>
#include <cuda_bf16.h>
#include <math.h>
#include <stdint.h>

#define TSEQ 512
#define KDIM 512
#define VOCAB 32000
#define BT 2048

// ---------- scratch pools ----------
constexpr long E_H = 2048L*512, E_QKV = 2048L*4096, E_ATT = 32L*512*512,
               E_FF = 2048L*2048, E_W3 = 4L*4096*512, E_W12 = 4L*2048*512,
               E_UN = 32000L*512;
constexpr long O_HHI=0, O_HLO=O_HHI+E_H,
 O_QHI=O_HLO+E_H, O_QLO=O_QHI+E_QKV, O_KHI=O_QLO+E_QKV, O_KLO=O_KHI+E_QKV,
 O_VTHI=O_KLO+E_QKV, O_VTLO=O_VTHI+E_ATT, O_ATHI=O_VTLO+E_ATT, O_ATLO=O_ATHI+E_ATT,
 O_YHI=O_ATLO+E_ATT, O_YLO=O_YHI+E_QKV, O_FHI=O_YLO+E_QKV, O_FLO=O_FHI+E_FF,
 O_WQHI=O_FLO+E_FF, O_WQLO=O_WQHI+E_W3, O_WKHI=O_WQLO+E_W3, O_WKLO=O_WKHI+E_W3,
 O_WVHI=O_WKLO+E_W3, O_WVLO=O_WVHI+E_W3, O_WUHI=O_WVLO+E_W3, O_WULO=O_WUHI+E_W3,
 O_W1HI=O_WULO+E_W3, O_W1LO=O_W1HI+E_W12, O_W2HI=O_W1LO+E_W12, O_W2LO=O_W2HI+E_W12,
 O_UNHI=O_W2LO+E_W12, O_UNLO=O_UNHI+E_UN, BF_TOTAL=O_UNLO+E_UN;
__device__ __nv_bfloat16 g_bf[BF_TOTAL];

constexpr long F_H=0, F_V=F_H+E_H, F_ATT=F_V+E_QKV, F_T1=F_ATT+E_ATT,
               F_TOTAL=F_T1+E_H;
__device__ float g_f[F_TOTAL];

// ---------- helpers ----------
__device__ __forceinline__ uint32_t s2u(const void* p) {
    uint32_t a;
    asm("{ .reg .u64 t; cvta.to.shared.u64 t, %1; cvt.u32.u64 %0, t; }" : "=r"(a) : "l"(p));
    return a;
}
__device__ __forceinline__ void ldm4(uint32_t& r0, uint32_t& r1, uint32_t& r2, uint32_t& r3,
                                     uint32_t addr) {
    asm volatile("ldmatrix.sync.aligned.m8n8.x4.shared.b16 {%0,%1,%2,%3}, [%4];"
                 : "=r"(r0), "=r"(r1), "=r"(r2), "=r"(r3) : "r"(addr));
}
__device__ __forceinline__ void mma16816(float* c, uint32_t a0, uint32_t a1, uint32_t a2,
                                         uint32_t a3, uint32_t b0, uint32_t b1) {
    asm volatile(
        "mma.sync.aligned.m16n8k16.row.col.f32.bf16.bf16.f32 "
        "{%0,%1,%2,%3}, {%4,%5,%6,%7}, {%8,%9}, {%0,%1,%2,%3};"
        : "+f"(c[0]), "+f"(c[1]), "+f"(c[2]), "+f"(c[3])
        : "r"(a0), "r"(a1), "r"(a2), "r"(a3), "r"(b0), "r"(b1));
}
__device__ __forceinline__ void cpa16(uint32_t dst, const void* src) {
    asm volatile("cp.async.cg.shared.global [%0], [%1], 16;" :: "r"(dst), "l"(src));
}
__device__ __forceinline__ void cpcommit() { asm volatile("cp.async.commit_group;"); }
__device__ __forceinline__ void cpwait0() { asm volatile("cp.async.wait_group 0;"); }
__device__ __forceinline__ void cpwait1() { asm volatile("cp.async.wait_group 1;"); }

__device__ __forceinline__ float gelu_exact(float x) {
    return 0.5f * x * (1.0f + erff(x * 0.70710678118654752f));
}
__device__ __forceinline__ void split_st(float v, __nv_bfloat16* hp, __nv_bfloat16* lp) {
    __nv_bfloat16 h = __float2bfloat16(v);
    *hp = h; *lp = __float2bfloat16(v - __bfloat162float(h));
}
__device__ __forceinline__ uint32_t pack_hi(float a, float b) {
    __nv_bfloat16 h0 = __float2bfloat16(a), h1 = __float2bfloat16(b);
    return (uint32_t)*(uint16_t*)&h0 | ((uint32_t)*(uint16_t*)&h1 << 16);
}
__device__ __forceinline__ uint32_t pack_lo(float a, float b) {
    __nv_bfloat16 h0 = __float2bfloat16(a), h1 = __float2bfloat16(b);
    float r0 = a - __bfloat162float(h0), r1 = b - __bfloat162float(h1);
    __nv_bfloat16 l0 = __float2bfloat16(r0), l1 = __float2bfloat16(r1);
    return (uint32_t)*(uint16_t*)&l0 | ((uint32_t)*(uint16_t*)&l1 << 16);
}
__device__ __forceinline__ float wSum(float v) {
    #pragma unroll
    for (int o = 16; o > 0; o >>= 1) v += __shfl_xor_sync(~0u, v, o);
    return v;
}
__device__ __forceinline__ float wMax(float v) {
    #pragma unroll
    for (int o = 16; o > 0; o >>= 1) v = fmaxf(v, __shfl_xor_sync(~0u, v, o));
    return v;
}

// ---------- split-bf16 HMMA GEMM: C[M,N] = alpha*A[M,K]*B[N,K]^T ----------
// Tile: (WM*64) x 128, 8 warps. WM=2: warp 64x32. WM=1: warp 64x16.
// K-chunk 32, cp.async 2-stage. SMEM rows 80B -> ldmatrix conflict-free.
constexpr int ROWB = 80;

template<int WM, bool SPLIT, bool BIAS, bool GELU, int CAUSAL>
__global__ void __launch_bounds__(256, 2)
tc_gemm(const __nv_bfloat16* __restrict__ Ah, const __nv_bfloat16* __restrict__ Al,
        int lda, long sAb, long sAh,
        const __nv_bfloat16* __restrict__ Bh, const __nv_bfloat16* __restrict__ Bl,
        int ldb, long sBb, long sBh,
        const float* __restrict__ bias,
        float* __restrict__ Cf, __nv_bfloat16* __restrict__ Chi, __nv_bfloat16* __restrict__ Clo,
        int ldc, long sCb, long sCh, int Kd, int Hdiv, float alpha)
{
    constexpr int MT  = WM * 64;           // M tile
    constexpr int WNW = 8 / WM;            // warps along N
    constexpr int NW  = 128 / WNW;         // warp n-width (16*WM)
    constexpr int NFR = NW / 8;            // n fragments per warp
    constexpr int APL = MT * ROWB;         // A plane bytes
    constexpr int BPL = 128 * ROWB;        // B plane bytes
    constexpr int STGB = 2 * APL + 2 * BPL;

    const int m0 = blockIdx.y * MT, n0 = blockIdx.x * 128;
    if (CAUSAL == 1 && n0 > m0 + MT - 1) return;

    const int bz = blockIdx.z, bb = bz / Hdiv, hh = bz - bb * Hdiv;
    Ah += (long)bb*sAb + (long)hh*sAh;  Al += (long)bb*sAb + (long)hh*sAh;
    Bh += (long)bb*sBb + (long)hh*sBh;  Bl += (long)bb*sBb + (long)hh*sBh;
    const long coff = (long)bb*sCb + (long)hh*sCh;

    extern __shared__ char smem[];
    const uint32_t sb = s2u(smem);
    const int tid = threadIdx.x, wid = tid >> 5, lane = tid & 31;
    const int wm = wid / WNW, wn = wid % WNW;

    int nk = Kd >> 5;
    if (CAUSAL == 2) { int kl = m0 + MT; if (kl > Kd) kl = Kd; nk = kl >> 5; }

    float acc[4][NFR][4];
    #pragma unroll
    for (int i = 0; i < 4; i++)
        #pragma unroll
        for (int j = 0; j < NFR; j++)
            #pragma unroll
            for (int q = 0; q < 4; q++) acc[i][j][q] = 0.0f;

    auto load_stage = [&](int st, int kt) {
        const int k0 = kt << 5;
        const uint32_t base = sb + st * STGB;
        // A: 2 planes x MT rows x 4 chunks
        #pragma unroll
        for (int it = 0; it < MT / 32; it++) {
            int id = it * 256 + tid;
            int plane = id / (MT * 4), rem = id % (MT * 4), r = rem >> 2, c = rem & 3;
            const __nv_bfloat16* src = plane ? Al : Ah;
            cpa16(base + plane * APL + r * ROWB + c * 16,
                  src + (long)(m0 + r) * lda + k0 + c * 8);
        }
        // B: 2 planes x 128 rows x 4 chunks
        #pragma unroll
        for (int it = 0; it < 4; it++) {
            int id = it * 256 + tid;
            int plane = id >> 9, rem = id & 511, r = rem >> 2, c = rem & 3;
            const __nv_bfloat16* src = plane ? Bl : Bh;
            cpa16(base + 2 * APL + plane * BPL + r * ROWB + c * 16,
                  src + (long)(n0 + r) * ldb + k0 + c * 8);
        }
    };

    load_stage(0, 0);
    cpcommit();

    for (int kt = 0; kt < nk; kt++) {
        const int st = kt & 1;
        if (kt + 1 < nk) { load_stage(st ^ 1, kt + 1); cpcommit(); cpwait1(); }
        else cpwait0();
        __syncthreads();

        const uint32_t stg = sb + st * STGB;
        #pragma unroll
        for (int kk = 0; kk < 2; kk++) {
            // B fragments (hoisted)
            uint32_t bh[NFR][2], bl[NFR][2];
            {
                const int q = lane >> 3, w8 = lane & 7;
                const uint32_t rofs = (uint32_t)(wn * NW + w8 + ((q >> 1) << 3)) * ROWB
                                    + kk * 32 + ((q & 1) << 4);
                #pragma unroll
                for (int np = 0; np < NFR / 2; np++) {
                    uint32_t bd = stg + 2 * APL + rofs + (uint32_t)(np * 16) * ROWB;
                    uint32_t r0, r1, r2, r3;
                    ldm4(r0, r1, r2, r3, bd);
                    bh[np*2][0] = r0; bh[np*2][1] = r1;
                    bh[np*2+1][0] = r2; bh[np*2+1][1] = r3;
                    ldm4(r0, r1, r2, r3, bd + BPL);
                    bl[np*2][0] = r0; bl[np*2][1] = r1;
                    bl[np*2+1][0] = r2; bl[np*2+1][1] = r3;
                }
            }
            // A per-mf, 3-term MMA
            const uint32_t rofsA = (uint32_t)(wm * 64 + (lane & 15)) * ROWB
                                 + kk * 32 + ((lane >> 4) << 4);
            #pragma unroll
            for (int mf = 0; mf < 4; mf++) {
                uint32_t a0, a1, a2, a3, l0, l1, l2, l3;
                uint32_t ad = stg + rofsA + (uint32_t)(mf * 16) * ROWB;
                ldm4(a0, a1, a2, a3, ad);
                ldm4(l0, l1, l2, l3, ad + APL);
                #pragma unroll
                for (int nf = 0; nf < NFR; nf++) {
                    mma16816(acc[mf][nf], a0, a1, a2, a3, bh[nf][0], bh[nf][1]);
                    mma16816(acc[mf][nf], a0, a1, a2, a3, bl[nf][0], bl[nf][1]);
                    mma16816(acc[mf][nf], l0, l1, l2, l3, bh[nf][0], bh[nf][1]);
                }
            }
        }
        __syncthreads();
    }

    // ---- epilogue ----
    const int mbase = m0 + wm * 64 + (lane >> 2);
    const int nbase = n0 + wn * NW + (lane & 3) * 2;
    #pragma unroll
    for (int mf = 0; mf < 4; mf++) {
        #pragma unroll
        for (int nf = 0; nf < NFR; nf++) {
            const int m = mbase + mf * 16, n = nbase + nf * 8;
            float v0 = acc[mf][nf][0] * alpha, v1 = acc[mf][nf][1] * alpha;
            float v2 = acc[mf][nf][2] * alpha, v3 = acc[mf][nf][3] * alpha;
            if (BIAS) {
                float bb0 = bias[n], bb1 = bias[n + 1];
                v0 += bb0; v1 += bb1; v2 += bb0; v3 += bb1;
            }
            if (GELU) {
                v0 = gelu_exact(v0); v1 = gelu_exact(v1);
                v2 = gelu_exact(v2); v3 = gelu_exact(v3);
            }
            const long r0 = coff + (long)m * ldc + n;
            const long r1 = coff + (long)(m + 8) * ldc + n;
            if (!SPLIT) {
                *(float2*)(Cf + r0) = make_float2(v0, v1);
                *(float2*)(Cf + r1) = make_float2(v2, v3);
            } else {
                *(uint32_t*)(Chi + r0) = pack_hi(v0, v1);
                *(uint32_t*)(Clo + r0) = pack_lo(v0, v1);
                *(uint32_t*)(Chi + r1) = pack_hi(v2, v3);
                *(uint32_t*)(Clo + r1) = pack_lo(v2, v3);
            }
        }
    }
}

constexpr int SMEM_WM2 = 2 * (2 * 128 * ROWB + 2 * 128 * ROWB);  // 81920
constexpr int SMEM_WM1 = 2 * (2 * 64 * ROWB + 2 * 128 * ROWB);   // 61440

// ---------- transpose + split: out[C,R] = in[R,C] ----------
__global__ void tsplit_ker(const float* __restrict__ in, int ldin, long sInB, long sInH,
                           __nv_bfloat16* __restrict__ oh, __nv_bfloat16* __restrict__ ol,
                           int ldout, long sOutB, long sOutH, int Hdiv)
{
    __shared__ float t[32][33];
    const int bz = blockIdx.z, bb = bz / Hdiv, hh = bz - bb * Hdiv;
    in += (long)bb*sInB + (long)hh*sInH;
    oh += (long)bb*sOutB + (long)hh*sOutH;
    ol += (long)bb*sOutB + (long)hh*sOutH;
    const int c0 = blockIdx.x * 32, r0 = blockIdx.y * 32;
    const int tx = threadIdx.x, ty = threadIdx.y;
    #pragma unroll
    for (int i = 0; i < 4; i++) {
        int r = ty + i * 8;
        t[r][tx] = in[(long)(r0 + r) * ldin + c0 + tx];
    }
    __syncthreads();
    #pragma unroll
    for (int i = 0; i < 4; i++) {
        int rr = ty + i * 8;
        long o = (long)(c0 + rr) * ldout + r0 + tx;
        split_st(t[tx][rr], oh + o, ol + o);
    }
}

// ---------- embed + positional ----------
__global__ void embed_ker(const int* __restrict__ x, const float* __restrict__ eW,
                          float* __restrict__ h,
                          __nv_bfloat16* __restrict__ hh, __nv_bfloat16* __restrict__ hl)
{
    long i = (long)blockIdx.x * blockDim.x + threadIdx.x;
    int d = (int)(i & 511);
    long bt = i >> 9;
    int t = (int)(bt & 511);
    int tok = x[bt];
    int j = d >> 1;
    float div = powf(10000.0f, (float)j * (1.0f / 128.0f));
    float ang = (float)t / div;
    float p = (d & 1) ? cosf(ang) : sinf(ang);
    float v = eW[(long)tok * 512 + d] + p;
    h[i] = v;
    split_st(v, hh + i, hl + i);
}

// ---------- causal softmax -> split ----------
__global__ void __launch_bounds__(256)
softmax_ker(const float* __restrict__ att,
            __nv_bfloat16* __restrict__ oh, __nv_bfloat16* __restrict__ ol)
{
    __shared__ float red[8];
    const int r = blockIdx.x, q = r & 511, tid = threadIdx.x;
    const float* row = att + (long)r * 512;
    float x0 = (tid       <= q) ? row[tid]       : -3.0e38f;
    float x1 = (tid + 256 <= q) ? row[tid + 256] : -3.0e38f;
    float m = wMax(fmaxf(x0, x1));
    if ((tid & 31) == 0) red[tid >> 5] = m;
    __syncthreads();
    m = red[0];
    #pragma unroll
    for (int i = 1; i < 8; i++) m = fmaxf(m, red[i]);
    __syncthreads();
    float e0 = (tid       <= q) ? expf(x0 - m) : 0.0f;
    float e1 = (tid + 256 <= q) ? expf(x1 - m) : 0.0f;
    float s = wSum(e0 + e1);
    if ((tid & 31) == 0) red[tid >> 5] = s;
    __syncthreads();
    s = red[0];
    #pragma unroll
    for (int i = 1; i < 8; i++) s += red[i];
    float inv = 1.0f / s;
    long base = (long)r * 512;
    split_st(e0 * inv, oh + base + tid,       ol + base + tid);
    split_st(e1 * inv, oh + base + tid + 256, ol + base + tid + 256);
}

// ---------- (residual+) LayerNorm -> fp32 + split ----------
__global__ void __launch_bounds__(256)
ln_ker(const float* __restrict__ in, const float* __restrict__ res,
       const float* __restrict__ w, const float* __restrict__ b,
       float* __restrict__ out, __nv_bfloat16* __restrict__ oh, __nv_bfloat16* __restrict__ ol)
{
    __shared__ float red[8];
    const int r = blockIdx.x, tid = threadIdx.x;
    const long base = (long)r * 512;
    float x0 = in[base + tid], x1 = in[base + tid + 256];
    if (res) { x0 += res[base + tid]; x1 += res[base + tid + 256]; }
    float s = wSum(x0 + x1);
    if ((tid & 31) == 0) red[tid >> 5] = s;
    __syncthreads();
    float tot = red[0];
    #pragma unroll
    for (int i = 1; i < 8; i++) tot += red[i];
    float mean = tot * (1.0f / 512.0f);
    __syncthreads();
    float d0 = x0 - mean, d1 = x1 - mean;
    float s2 = wSum(d0 * d0 + d1 * d1);
    if ((tid & 31) == 0) red[tid >> 5] = s2;
    __syncthreads();
    float v = red[0];
    #pragma unroll
    for (int i = 1; i < 8; i++) v += red[i];
    float inv = 1.0f / sqrtf(v * (1.0f / 512.0f) + 1e-5f);
    float y0 = d0 * inv * w[tid]       + b[tid];
    float y1 = d1 * inv * w[tid + 256] + b[tid + 256];
    out[base + tid] = y0; out[base + tid + 256] = y1;
    split_st(y0, oh + base + tid,       ol + base + tid);
    split_st(y1, oh + base + tid + 256, ol + base + tid + 256);
}

// ---------- launch ----------
extern "C" void kernel_launch(void* const* d_in, const int* in_sizes, int n_in,
                              void* d_out, int out_size)
{
    (void)in_sizes; (void)n_in; (void)out_size;
    const int*   x    = (const int*)  d_in[0];
    const float* eW   = (const float*)d_in[1];
    const float* Wq   = (const float*)d_in[2];
    const float* Wk   = (const float*)d_in[3];
    const float* Wv   = (const float*)d_in[4];
    const float* Wu   = (const float*)d_in[5];
    const float* bu   = (const float*)d_in[6];
    const float* W1   = (const float*)d_in[7];
    const float* b1   = (const float*)d_in[8];
    const float* W2   = (const float*)d_in[9];
    const float* b2   = (const float*)d_in[10];
    const float* ln1w = (const float*)d_in[11];
    const float* ln1b = (const float*)d_in[12];
    const float* ln2w = (const float*)d_in[13];
    const float* ln2b = (const float*)d_in[14];
    const float* lnfw = (const float*)d_in[15];
    const float* lnfb = (const float*)d_in[16];
    const float* uW   = (const float*)d_in[17];
    const float* ub   = (const float*)d_in[18];
    float* outp = (float*)d_out;

    void *pb = nullptr, *pf = nullptr;
    cudaGetSymbolAddress(&pb, g_bf);
    cudaGetSymbolAddress(&pf, g_f);
    __nv_bfloat16* B = (__nv_bfloat16*)pb;
    float* F = (float*)pf;

    cudaFuncSetAttribute(tc_gemm<2,true,false,false,0>, cudaFuncAttributeMaxDynamicSharedMemorySize, SMEM_WM2);
    cudaFuncSetAttribute(tc_gemm<2,false,false,false,0>, cudaFuncAttributeMaxDynamicSharedMemorySize, SMEM_WM2);
    cudaFuncSetAttribute(tc_gemm<2,false,false,false,1>, cudaFuncAttributeMaxDynamicSharedMemorySize, SMEM_WM2);
    cudaFuncSetAttribute(tc_gemm<2,true,false,false,2>, cudaFuncAttributeMaxDynamicSharedMemorySize, SMEM_WM2);
    cudaFuncSetAttribute(tc_gemm<1,false,true,false,0>, cudaFuncAttributeMaxDynamicSharedMemorySize, SMEM_WM1);
    cudaFuncSetAttribute(tc_gemm<2,true,true,true,0>, cudaFuncAttributeMaxDynamicSharedMemorySize, SMEM_WM2);
    cudaFuncSetAttribute(tc_gemm<2,false,true,false,0>, cudaFuncAttributeMaxDynamicSharedMemorySize, SMEM_WM2);

    const dim3 t8(32, 8);
    // weight transpose+split
    tsplit_ker<<<dim3(128,16,4), t8>>>(Wq, 4096, 512L*4096, 0, B+O_WQHI, B+O_WQLO, 512, 4096L*512, 0, 1);
    tsplit_ker<<<dim3(128,16,4), t8>>>(Wk, 4096, 512L*4096, 0, B+O_WKHI, B+O_WKLO, 512, 4096L*512, 0, 1);
    tsplit_ker<<<dim3(128,16,4), t8>>>(Wv, 4096, 512L*4096, 0, B+O_WVHI, B+O_WVLO, 512, 4096L*512, 0, 1);
    tsplit_ker<<<dim3(16,128,4), t8>>>(Wu,  512, 4096L*512, 0, B+O_WUHI, B+O_WULO, 4096, 512L*4096, 0, 1);
    tsplit_ker<<<dim3(64,16,4),  t8>>>(W1, 2048, 512L*2048, 0, B+O_W1HI, B+O_W1LO, 512, 2048L*512, 0, 1);
    tsplit_ker<<<dim3(16,64,4),  t8>>>(W2,  512, 2048L*512, 0, B+O_W2HI, B+O_W2LO, 2048, 512L*2048, 0, 1);
    tsplit_ker<<<dim3(1000,16,1),t8>>>(uW, 32000, 0, 0, B+O_UNHI, B+O_UNLO, 512, 0, 0, 1);

    embed_ker<<<(BT*512)/256, 256>>>(x, eW, F+F_H, B+O_HHI, B+O_HLO);

    const float isk = 0.04419417382415922f; // 1/sqrt(512)
    const dim3 gQKV(32,16,1), gATT(4,4,32), gOUT64(4,32,1), gFF(16,16,1);

    for (int i = 0; i < 4; i++) {
        const long w3 = (long)i * 4096 * 512, w12 = (long)i * 2048 * 512;
        tc_gemm<2,true,false,false,0><<<gQKV,256,SMEM_WM2>>>(B+O_HHI, B+O_HLO, 512,0,0,
            B+O_WQHI+w3, B+O_WQLO+w3, 512,0,0, nullptr,
            nullptr, B+O_QHI, B+O_QLO, 4096,0,0, 512, 1, 1.0f);
        tc_gemm<2,true,false,false,0><<<gQKV,256,SMEM_WM2>>>(B+O_HHI, B+O_HLO, 512,0,0,
            B+O_WKHI+w3, B+O_WKLO+w3, 512,0,0, nullptr,
            nullptr, B+O_KHI, B+O_KLO, 4096,0,0, 512, 1, 1.0f);
        tc_gemm<2,false,false,false,0><<<gQKV,256,SMEM_WM2>>>(B+O_HHI, B+O_HLO, 512,0,0,
            B+O_WVHI+w3, B+O_WVLO+w3, 512,0,0, nullptr,
            F+F_V, nullptr, nullptr, 4096,0,0, 512, 1, 1.0f);
        // V^T split per (b,h): [t,d] -> [d,t]
        tsplit_ker<<<dim3(16,16,32), t8>>>(F+F_V, 4096, 512L*4096, 512,
            B+O_VTHI, B+O_VTLO, 512, 8L*512*512, 512L*512, 8);
        // scores = Q K^T / sqrt(k), causal tile skip
        tc_gemm<2,false,false,false,1><<<gATT,256,SMEM_WM2>>>(
            B+O_QHI, B+O_QLO, 4096, 512L*4096, 512,
            B+O_KHI, B+O_KLO, 4096, 512L*4096, 512, nullptr,
            F+F_ATT, nullptr, nullptr, 512, 8L*512*512, 512L*512, 512, 8, isk);
        softmax_ker<<<32*512, 256>>>(F+F_ATT, B+O_ATHI, B+O_ATLO);
        // y = att @ V (K-limit from causality)
        tc_gemm<2,true,false,false,2><<<gATT,256,SMEM_WM2>>>(
            B+O_ATHI, B+O_ATLO, 512, 8L*512*512, 512L*512,
            B+O_VTHI, B+O_VTLO, 512, 8L*512*512, 512L*512, nullptr,
            nullptr, B+O_YHI, B+O_YLO, 4096, 512L*4096, 512, 512, 8, 1.0f);
        // out proj + bu -> fp32 t1 (64-row tiles: 128 CTAs)
        tc_gemm<1,false,true,false,0><<<gOUT64,256,SMEM_WM1>>>(B+O_YHI, B+O_YLO, 4096,0,0,
            B+O_WUHI+w3, B+O_WULO+w3, 4096,0,0, bu + (long)i*512,
            F+F_T1, nullptr, nullptr, 512,0,0, 4096, 1, 1.0f);
        ln_ker<<<BT,256>>>(F+F_T1, F+F_H, ln1w+(long)i*512, ln1b+(long)i*512,
                           F+F_H, B+O_HHI, B+O_HLO);
        // FFN up + GELU (split out)
        tc_gemm<2,true,true,true,0><<<gFF,256,SMEM_WM2>>>(B+O_HHI, B+O_HLO, 512,0,0,
            B+O_W1HI+w12, B+O_W1LO+w12, 512,0,0, b1 + (long)i*2048,
            nullptr, B+O_FHI, B+O_FLO, 2048,0,0, 512, 1, 1.0f);
        // FFN down + b2 -> fp32 t1 (64-row tiles)
        tc_gemm<1,false,true,false,0><<<gOUT64,256,SMEM_WM1>>>(B+O_FHI, B+O_FLO, 2048,0,0,
            B+O_W2HI+w12, B+O_W2LO+w12, 2048,0,0, b2 + (long)i*512,
            F+F_T1, nullptr, nullptr, 512,0,0, 2048, 1, 1.0f);
        ln_ker<<<BT,256>>>(F+F_T1, F+F_H, ln2w+(long)i*512, ln2b+(long)i*512,
                           F+F_H, B+O_HHI, B+O_HLO);
    }
    // final LN (no residual)
    ln_ker<<<BT,256>>>(F+F_H, nullptr, lnfw, lnfb, F+F_T1, B+O_HHI, B+O_HLO);
    // unembed
    tc_gemm<2,false,true,false,0><<<dim3(250,16,1),256,SMEM_WM2>>>(B+O_HHI, B+O_HLO, 512,0,0,
        B+O_UNHI, B+O_UNLO, 512,0,0, ub,
        outp, nullptr, nullptr, 32000,0,0, 512, 1, 1.0f);
}